// round 9
// baseline (speedup 1.0000x reference)
#include <cuda_runtime.h>

#define N_POINTS 300000
#define N_PAIRS  100000
#define K_OFFSETS 27
#define C_IN 32
#define C_OUT 64
#define GROUPS 8
#define EPS_GN 1e-5f
#define NEG_SLOPE 0.01f

typedef unsigned long long ull;

// ---------------- device scratch (no allocations allowed) ----------------
__device__ float g_sum[GROUPS];
__device__ float g_sqs[GROUPS];
__device__ unsigned g_done;
__device__ __align__(16) float g_scale[C_OUT];
__device__ __align__(16) float g_bias[C_OUT];

// ---------------- f32x2 packed-math helpers (Blackwell) ------------------
__device__ __forceinline__ ull pk2(float lo, float hi) {
    ull r;
    asm("mov.b64 %0, {%1, %2};" : "=l"(r) : "f"(lo), "f"(hi));
    return r;
}
__device__ __forceinline__ void unpk2(ull v, float& lo, float& hi) {
    asm("mov.b64 {%0, %1}, %2;" : "=f"(lo), "=f"(hi) : "l"(v));
}
__device__ __forceinline__ ull fma2(ull a, ull b, ull c) {
    ull d;
    asm("fma.rn.f32x2 %0, %1, %2, %3;" : "=l"(d) : "l"(a), "l"(b), "l"(c));
    return d;
}
__device__ __forceinline__ ull add2(ull a, ull b) {
    ull d;
    asm("add.rn.f32x2 %0, %1, %2;" : "=l"(d) : "l"(a), "l"(b));
    return d;
}
// combine lane with partner (lane ^ 16) on a packed accumulator
__device__ __forceinline__ ull halfcomb(ull v) {
    return add2(v, __shfl_xor_sync(0xffffffffu, v, 16));
}
__device__ __forceinline__ void red4(float* dst, ull lo, ull hi) {
    float r0, r1, r2, r3;
    unpk2(lo, r0, r1);
    unpk2(hi, r2, r3);
    asm volatile("red.global.add.v4.f32 [%0], {%1, %2, %3, %4};"
                 :: "l"(dst), "f"(r0), "f"(r1), "f"(r2), "f"(r3) : "memory");
}

// ---------------- K0: zero output + zero scratch -------------------------
__global__ void zero_kernel(float4* __restrict__ out) {
    const int total4 = N_POINTS * C_OUT / 4;
    int i = blockIdx.x * blockDim.x + threadIdx.x;
    if (i < total4) out[i] = make_float4(0.f, 0.f, 0.f, 0.f);
    if (blockIdx.x == 0 && threadIdx.x < GROUPS) {
        g_sum[threadIdx.x] = 0.f;
        g_sqs[threadIdx.x] = 0.f;
        if (threadIdx.x == 0) g_done = 0u;
    }
}

// ---------------- K1: gather -> 32x64 matmul -> vector scatter-add -------
// One warp per QUAD of 4 contiguous pairs. Three-stage pipeline:
//   C: int4 index loads   B: feats gathers (idx from last iter)
//   A: stage to smem (duplicated), LDS-broadcast, compute, scatter
// Broadcast now goes through shared memory instead of shfl:
//   each lane STS.64 its (f,f) duplicated value; after one __syncwarp each
//   lane reads its 16 needed multipliers via 8 x LDS.128 (two fma2 operands
//   per load). The two half-warps' 16B chunks are INTERLEAVED so their
//   concurrent reads hit adjacent banks (no 128B-apart bank conflicts).
// Lane = hi*16 + q: hi = which half of C_IN this lane reduces,
//                   q  = owns output channels [4q, 4q+4).
__global__ void __launch_bounds__(256, 2)
conv_kernel(const float* __restrict__ feats,
            const float* __restrict__ weight,
            const int* __restrict__ in_idx,
            const int* __restrict__ out_idx,
            float* __restrict__ out) {
    // [parity][warp][pair][slot]: 2*8*4*32*8B = 16 KB
    __shared__ __align__(16) ull sbuf[2][8][4][32];

    const int k    = blockIdx.y;
    const int lane = threadIdx.x & 31;
    const int wid  = threadIdx.x >> 5;
    const int hi   = lane >> 4;
    const int q    = lane & 15;
    const int c0   = q << 2;

    // interleaved store slot: chunk c = 2*jj + hi holds channels (hi,2jj,2jj+1)
    const int stidx = ((lane & 14) << 1) | ((lane >> 3) & 2) | (lane & 1);

    // Weight slice for this lane: i = hi*16 + j, channels c0..c0+3
    ull w0[16], w1[16];
    const float* wk = weight + (size_t)k * (C_IN * C_OUT);
    #pragma unroll
    for (int j = 0; j < 16; ++j) {
        float4 v = *(const float4*)(wk + (size_t)(hi * 16 + j) * C_OUT + c0);
        w0[j] = pk2(v.x, v.y);
        w1[j] = pk2(v.z, v.w);
    }

    const int* ik = in_idx  + (size_t)k * N_PAIRS;
    const int* ok = out_idx + (size_t)k * N_PAIRS;

    const int wg      = blockIdx.x * (blockDim.x >> 5) + wid;
    const int qstride = (gridDim.x * (blockDim.x >> 5)) << 2; // pairs/sweep

    // ---- prologue ----
    int bA = wg << 2;
    bool vA = bA < N_PAIRS;
    int4 oA = make_int4(0, 0, 0, 0);
    float fA0 = 0.f, fA1 = 0.f, fA2 = 0.f, fA3 = 0.f;
    if (vA) {
        int4 ia = *(const int4*)(ik + bA);
        oA      = *(const int4*)(ok + bA);
        fA0 = feats[(size_t)ia.x * C_IN + lane];
        fA1 = feats[(size_t)ia.y * C_IN + lane];
        fA2 = feats[(size_t)ia.z * C_IN + lane];
        fA3 = feats[(size_t)ia.w * C_IN + lane];
    }
    int bB = bA + qstride;
    bool vB = bB < N_PAIRS;
    int4 iB = make_int4(0, 0, 0, 0), oB = make_int4(0, 0, 0, 0);
    if (vB) { iB = *(const int4*)(ik + bB); oB = *(const int4*)(ok + bB); }
    int bC = bB + qstride;

    int par = 0;
    while (vA) {
        // -- stage A part 1: store duplicated feats for broadcast --
        sbuf[par][wid][0][stidx] = pk2(fA0, fA0);
        sbuf[par][wid][1][stidx] = pk2(fA1, fA1);
        sbuf[par][wid][2][stidx] = pk2(fA2, fA2);
        sbuf[par][wid][3][stidx] = pk2(fA3, fA3);
        __syncwarp(0xffffffffu);

        // -- stage B: issue feats gathers (indices already resident) --
        float fB0 = 0.f, fB1 = 0.f, fB2 = 0.f, fB3 = 0.f;
        if (vB) {
            fB0 = feats[(size_t)iB.x * C_IN + lane];
            fB1 = feats[(size_t)iB.y * C_IN + lane];
            fB2 = feats[(size_t)iB.z * C_IN + lane];
            fB3 = feats[(size_t)iB.w * C_IN + lane];
        }
        // -- stage C: load next indices --
        const bool vC = bC < N_PAIRS;
        int4 iC = make_int4(0, 0, 0, 0), oC = make_int4(0, 0, 0, 0);
        if (vC) { iC = *(const int4*)(ik + bC); oC = *(const int4*)(ok + bC); }

        // -- stage A part 2: LDS-broadcast + 8 independent FMA2 chains --
        ull a00 = 0ull, a01 = 0ull, a10 = 0ull, a11 = 0ull;
        ull a20 = 0ull, a21 = 0ull, a30 = 0ull, a31 = 0ull;
        {
            const ulonglong2* s0 = (const ulonglong2*)&sbuf[par][wid][0][0];
            const ulonglong2* s1 = (const ulonglong2*)&sbuf[par][wid][1][0];
            const ulonglong2* s2 = (const ulonglong2*)&sbuf[par][wid][2][0];
            const ulonglong2* s3 = (const ulonglong2*)&sbuf[par][wid][3][0];
            #pragma unroll
            for (int jj = 0; jj < 8; ++jj) {
                const int c = 2 * jj + hi;        // interleaved chunk index
                ulonglong2 m0 = s0[c];
                ulonglong2 m1 = s1[c];
                ulonglong2 m2 = s2[c];
                ulonglong2 m3 = s3[c];
                const int j0 = 2 * jj, j1 = 2 * jj + 1;
                a00 = fma2(m0.x, w0[j0], a00);  a01 = fma2(m0.x, w1[j0], a01);
                a00 = fma2(m0.y, w0[j1], a00);  a01 = fma2(m0.y, w1[j1], a01);
                a10 = fma2(m1.x, w0[j0], a10);  a11 = fma2(m1.x, w1[j0], a11);
                a10 = fma2(m1.y, w0[j1], a10);  a11 = fma2(m1.y, w1[j1], a11);
                a20 = fma2(m2.x, w0[j0], a20);  a21 = fma2(m2.x, w1[j0], a21);
                a20 = fma2(m2.y, w0[j1], a20);  a21 = fma2(m2.y, w1[j1], a21);
                a30 = fma2(m3.x, w0[j0], a30);  a31 = fma2(m3.x, w1[j0], a31);
                a30 = fma2(m3.y, w0[j1], a30);  a31 = fma2(m3.y, w1[j1], a31);
            }
        }

        // packed half-combine (8 parallel chains)
        a00 = halfcomb(a00);  a01 = halfcomb(a01);
        a10 = halfcomb(a10);  a11 = halfcomb(a11);
        a20 = halfcomb(a20);  a21 = halfcomb(a21);
        a30 = halfcomb(a30);  a31 = halfcomb(a31);

        if (hi == 0) {
            red4(out + (size_t)oA.x * C_OUT + c0, a00, a01);
            red4(out + (size_t)oA.y * C_OUT + c0, a10, a11);
            red4(out + (size_t)oA.z * C_OUT + c0, a20, a21);
            red4(out + (size_t)oA.w * C_OUT + c0, a30, a31);
        }

        // -- rotate pipeline --
        fA0 = fB0; fA1 = fB1; fA2 = fB2; fA3 = fB3;
        oA = oB; vA = vB;
        iB = iC; oB = oC; vB = vC;
        bC += qstride;
        par ^= 1;
    }
}

// ---------------- K2: group stats + (last block) fold params -------------
__global__ void stats_kernel(const float* __restrict__ out,
                             const float* __restrict__ gamma,
                             const float* __restrict__ beta) {
    float s[GROUPS], ss[GROUPS];
    #pragma unroll
    for (int g = 0; g < GROUPS; ++g) { s[g] = 0.f; ss[g] = 0.f; }

    const int tid = blockIdx.x * blockDim.x + threadIdx.x;
    const int nth = gridDim.x * blockDim.x;
    for (int r = tid; r < N_POINTS; r += nth) {
        const float4* row = (const float4*)(out + (size_t)r * C_OUT);
        #pragma unroll
        for (int g = 0; g < GROUPS; ++g) {
            float4 a = row[2 * g];
            float4 b = row[2 * g + 1];
            s[g]  += ((a.x + a.y) + (a.z + a.w)) + ((b.x + b.y) + (b.z + b.w));
            ss[g] += ((a.x * a.x + a.y * a.y) + (a.z * a.z + a.w * a.w)) +
                     ((b.x * b.x + b.y * b.y) + (b.z * b.z + b.w * b.w));
        }
    }
    #pragma unroll
    for (int g = 0; g < GROUPS; ++g) {
        #pragma unroll
        for (int off = 16; off > 0; off >>= 1) {
            s[g]  += __shfl_xor_sync(0xffffffffu, s[g],  off);
            ss[g] += __shfl_xor_sync(0xffffffffu, ss[g], off);
        }
    }
    if ((threadIdx.x & 31) == 0) {
        #pragma unroll
        for (int g = 0; g < GROUPS; ++g) {
            atomicAdd(&g_sum[g], s[g]);
            atomicAdd(&g_sqs[g], ss[g]);
        }
    }
    __syncthreads();
    if (threadIdx.x == 0) {
        __threadfence();
        unsigned t = atomicInc(&g_done, 0xffffffffu);
        if (t == gridDim.x - 1) {   // last block folds mean/var/gamma/beta
            const float n = (float)N_POINTS * (float)(C_OUT / GROUPS);
            #pragma unroll
            for (int c = 0; c < C_OUT; ++c) {
                int g = c >> 3;
                float mean = g_sum[g] / n;
                float var  = g_sqs[g] / n - mean * mean;
                float rs   = rsqrtf(var + EPS_GN);
                float sc   = gamma[c] * rs;
                g_scale[c] = sc;
                g_bias[c]  = beta[c] - mean * sc;
            }
        }
    }
}

// ---------------- K3: normalize + LeakyReLU (in place) -------------------
__global__ void norm_kernel(float4* __restrict__ out) {
    const int total4 = N_POINTS * C_OUT / 4;
    int i = blockIdx.x * blockDim.x + threadIdx.x;
    if (i >= total4) return;
    int q = i & 15;  // which float4 within the 64-channel row
    float4 sc = ((const float4*)g_scale)[q];
    float4 bs = ((const float4*)g_bias)[q];
    float4 v = out[i];
    v.x = v.x * sc.x + bs.x; v.x = (v.x >= 0.f) ? v.x : NEG_SLOPE * v.x;
    v.y = v.y * sc.y + bs.y; v.y = (v.y >= 0.f) ? v.y : NEG_SLOPE * v.y;
    v.z = v.z * sc.z + bs.z; v.z = (v.z >= 0.f) ? v.z : NEG_SLOPE * v.z;
    v.w = v.w * sc.w + bs.w; v.w = (v.w >= 0.f) ? v.w : NEG_SLOPE * v.w;
    out[i] = v;
}

// ---------------- launch ---------------------------------------------------
extern "C" void kernel_launch(void* const* d_in, const int* in_sizes, int n_in,
                              void* d_out, int out_size) {
    const float* feats   = (const float*)d_in[0];   // [N, 32]
    const float* weight  = (const float*)d_in[1];   // [27, 32, 64]
    const float* gamma   = (const float*)d_in[2];   // [64]
    const float* beta    = (const float*)d_in[3];   // [64]
    const int*   in_idx  = (const int*)d_in[4];     // [27, 100000] int32
    const int*   out_idx = (const int*)d_in[5];     // [27, 100000] int32
    float* out = (float*)d_out;                     // [N, 64]

    const int total4 = N_POINTS * C_OUT / 4;
    const int zblocks = (total4 + 255) / 256;

    zero_kernel<<<zblocks, 256>>>((float4*)out);

    // 21 x 27 = 567 CTAs <= 592 resident (148 SMs x occ 2) -> exactly 2 waves.
    dim3 cgrid(21, K_OFFSETS);
    conv_kernel<<<cgrid, 256>>>(feats, weight, in_idx, out_idx, out);

    stats_kernel<<<296, 256>>>(out, gamma, beta);
    norm_kernel<<<zblocks, 256>>>((float4*)out);
}